// round 1
// baseline (speedup 1.0000x reference)
#include <cuda_runtime.h>

#define N_NODES 100000
#define N_EDGES 1600000
#define IN_F    256
#define HID     128
#define OUTF    64

// Scratch (device globals: allocation-free per harness rules)
__device__ float g_h1[(size_t)N_NODES * HID];   // X@W1
__device__ float g_h2[(size_t)N_NODES * HID];   // spmm(h1)
__device__ float g_h4[(size_t)N_NODES * OUTF];  // relu(h2+b1)@W2

// Vectorized fp32 reduction to global (sm_90+): 4 floats per atomic op.
__device__ __forceinline__ void red_add_v4(float* p, float x, float y, float z, float w) {
    asm volatile("red.global.add.v4.f32 [%0], {%1, %2, %3, %4};"
                 :: "l"(p), "f"(x), "f"(y), "f"(z), "f"(w) : "memory");
}

// ---------------------------------------------------------------------------
// zero h2
// ---------------------------------------------------------------------------
__global__ void zero_h2_kernel() {
    size_t i = (size_t)blockIdx.x * blockDim.x + threadIdx.x;
    size_t n = (size_t)N_NODES * HID / 4;
    if (i < n) ((float4*)g_h2)[i] = make_float4(0.f, 0.f, 0.f, 0.f);
}

// ---------------------------------------------------------------------------
// GEMM1: g_h1[M,128] = X[M,256] @ W1[256,128]
// Block tile 64x128, BK=16, 256 threads, thread tile 8x4.
// ---------------------------------------------------------------------------
__global__ __launch_bounds__(256) void gemm1_kernel(const float* __restrict__ X,
                                                    const float* __restrict__ W1) {
    __shared__ float As[16 * 64];    // [k][m] transposed
    __shared__ float Bs[16 * HID];   // [k][n]

    const int tid  = threadIdx.x;
    const int brow = blockIdx.x * 64;
    const int tx   = tid & 31;   // col group (x4)
    const int ty   = tid >> 5;   // row group (x8)

    float acc[8][4];
#pragma unroll
    for (int i = 0; i < 8; i++)
#pragma unroll
        for (int j = 0; j < 4; j++) acc[i][j] = 0.f;

    const int  arow   = tid >> 2;         // 0..63
    const int  ak     = (tid & 3) << 2;   // 0,4,8,12
    const int  grow   = brow + arow;
    const bool avalid = grow < N_NODES;

    for (int k0 = 0; k0 < IN_F; k0 += 16) {
        float4 av = make_float4(0.f, 0.f, 0.f, 0.f);
        if (avalid) av = *(const float4*)(X + (size_t)grow * IN_F + k0 + ak);
        As[(ak + 0) * 64 + arow] = av.x;
        As[(ak + 1) * 64 + arow] = av.y;
        As[(ak + 2) * 64 + arow] = av.z;
        As[(ak + 3) * 64 + arow] = av.w;

#pragma unroll
        for (int i = 0; i < 2; i++) {
            int f  = tid * 2 + i;          // 0..511 float4s of 16x128 tile
            int br = f >> 5;               // k row 0..15
            int bc = (f & 31) << 2;        // col
            *(float4*)(Bs + br * HID + bc) =
                *(const float4*)(W1 + (size_t)(k0 + br) * HID + bc);
        }
        __syncthreads();

#pragma unroll
        for (int k = 0; k < 16; k++) {
            float4 b   = *(float4*)(Bs + k * HID + tx * 4);
            float4 alo = *(float4*)(As + k * 64 + ty * 8);
            float4 ahi = *(float4*)(As + k * 64 + ty * 8 + 4);
            float a[8] = {alo.x, alo.y, alo.z, alo.w, ahi.x, ahi.y, ahi.z, ahi.w};
            float bb[4] = {b.x, b.y, b.z, b.w};
#pragma unroll
            for (int i = 0; i < 8; i++)
#pragma unroll
                for (int j = 0; j < 4; j++) acc[i][j] += a[i] * bb[j];
        }
        __syncthreads();
    }

#pragma unroll
    for (int i = 0; i < 8; i++) {
        int r = brow + ty * 8 + i;
        if (r < N_NODES)
            *(float4*)(g_h1 + (size_t)r * HID + tx * 4) =
                make_float4(acc[i][0], acc[i][1], acc[i][2], acc[i][3]);
    }
}

// ---------------------------------------------------------------------------
// SpMM1: g_h2[row] += vals * g_h1[col]  (warp per edge, float4 per lane)
// ---------------------------------------------------------------------------
__global__ void spmm1_kernel(const int* __restrict__ row,
                             const int* __restrict__ col,
                             const float* __restrict__ vals) {
    long long t = (long long)blockIdx.x * blockDim.x + threadIdx.x;
    int e    = (int)(t >> 5);
    int lane = (int)(t & 31);
    if (e >= N_EDGES) return;
    int   r = __ldg(row + e);
    int   c = __ldg(col + e);
    float v = __ldg(vals + e);
    const float4 s = *(const float4*)(g_h1 + (size_t)c * HID + lane * 4);
    red_add_v4(g_h2 + (size_t)r * HID + lane * 4, s.x * v, s.y * v, s.z * v, s.w * v);
}

// ---------------------------------------------------------------------------
// GEMM2 (fused): g_h4[M,64] = relu(g_h2 + b1) @ W2[128,64]
// Block tile 64x64, BK=16, 256 threads, thread tile 4x4.
// ---------------------------------------------------------------------------
__global__ __launch_bounds__(256) void gemm2_kernel(const float* __restrict__ B1,
                                                    const float* __restrict__ W2) {
    __shared__ float As[16 * 64];   // [k][m]
    __shared__ float Bs[16 * 64];   // [k][n]
    __shared__ float b1s[HID];

    const int tid = threadIdx.x;
    if (tid < HID) b1s[tid] = B1[tid];

    const int brow = blockIdx.x * 64;
    const int tx   = tid & 15;   // col group (x4)
    const int ty   = tid >> 4;   // row group (x4)

    float acc[4][4];
#pragma unroll
    for (int i = 0; i < 4; i++)
#pragma unroll
        for (int j = 0; j < 4; j++) acc[i][j] = 0.f;

    const int  arow   = tid >> 2;
    const int  ak     = (tid & 3) << 2;
    const int  grow   = brow + arow;
    const bool avalid = grow < N_NODES;

    __syncthreads();   // b1s visible

    for (int k0 = 0; k0 < HID; k0 += 16) {
        float4 av = make_float4(0.f, 0.f, 0.f, 0.f);
        if (avalid) {
            av = *(const float4*)(g_h2 + (size_t)grow * HID + k0 + ak);
            av.x = fmaxf(av.x + b1s[k0 + ak + 0], 0.f);
            av.y = fmaxf(av.y + b1s[k0 + ak + 1], 0.f);
            av.z = fmaxf(av.z + b1s[k0 + ak + 2], 0.f);
            av.w = fmaxf(av.w + b1s[k0 + ak + 3], 0.f);
        }
        As[(ak + 0) * 64 + arow] = av.x;
        As[(ak + 1) * 64 + arow] = av.y;
        As[(ak + 2) * 64 + arow] = av.z;
        As[(ak + 3) * 64 + arow] = av.w;

        {
            int br = tid >> 4;            // 0..15
            int bc = (tid & 15) << 2;     // 0..60
            *(float4*)(Bs + br * 64 + bc) =
                *(const float4*)(W2 + (size_t)(k0 + br) * OUTF + bc);
        }
        __syncthreads();

#pragma unroll
        for (int k = 0; k < 16; k++) {
            float4 a = *(float4*)(As + k * 64 + ty * 4);
            float4 b = *(float4*)(Bs + k * 64 + tx * 4);
            float aa[4] = {a.x, a.y, a.z, a.w};
            float bb[4] = {b.x, b.y, b.z, b.w};
#pragma unroll
            for (int i = 0; i < 4; i++)
#pragma unroll
                for (int j = 0; j < 4; j++) acc[i][j] += aa[i] * bb[j];
        }
        __syncthreads();
    }

#pragma unroll
    for (int i = 0; i < 4; i++) {
        int r = brow + ty * 4 + i;
        if (r < N_NODES)
            *(float4*)(g_h4 + (size_t)r * OUTF + tx * 4) =
                make_float4(acc[i][0], acc[i][1], acc[i][2], acc[i][3]);
    }
}

// ---------------------------------------------------------------------------
// init out = broadcast b2
// ---------------------------------------------------------------------------
__global__ void init_out_kernel(float* __restrict__ out, const float* __restrict__ B2) {
    int i = blockIdx.x * blockDim.x + threadIdx.x;   // over N*64/4 float4s
    if (i < N_NODES * OUTF / 4) {
        int j = i & 15;                               // float4 index within row
        float4 b = *(const float4*)(B2 + j * 4);
        ((float4*)out)[i] = b;
    }
}

// ---------------------------------------------------------------------------
// SpMM2: out[row] += vals * g_h4[col]  (16 threads per edge, float4 each)
// ---------------------------------------------------------------------------
__global__ void spmm2_kernel(const int* __restrict__ row,
                             const int* __restrict__ col,
                             const float* __restrict__ vals,
                             float* __restrict__ out) {
    long long t = (long long)blockIdx.x * blockDim.x + threadIdx.x;
    int e = (int)(t >> 4);
    int j = (int)(t & 15);
    if (e >= N_EDGES) return;
    int   r = __ldg(row + e);
    int   c = __ldg(col + e);
    float v = __ldg(vals + e);
    const float4 s = *(const float4*)(g_h4 + (size_t)c * OUTF + j * 4);
    red_add_v4(out + (size_t)r * OUTF + j * 4, s.x * v, s.y * v, s.z * v, s.w * v);
}

// ---------------------------------------------------------------------------
extern "C" void kernel_launch(void* const* d_in, const int* in_sizes, int n_in,
                              void* d_out, int out_size) {
    const float* x       = (const float*)d_in[0];
    const float* w1      = (const float*)d_in[1];
    const float* b1      = (const float*)d_in[2];
    const float* w2      = (const float*)d_in[3];
    const float* b2      = (const float*)d_in[4];
    const int*   adj_row = (const int*)d_in[5];
    const int*   adj_col = (const int*)d_in[6];
    const float* vals    = (const float*)d_in[7];
    float*       out     = (float*)d_out;

    (void)in_sizes; (void)n_in; (void)out_size;

    // zero h2 accumulator
    {
        int n = N_NODES * HID / 4;
        zero_h2_kernel<<<(n + 255) / 256, 256>>>();
    }
    // h1 = X @ W1
    gemm1_kernel<<<(N_NODES + 63) / 64, 256>>>(x, w1);
    // h2 = A @ h1  (edge scatter, v4 reductions)
    {
        long long threads = (long long)N_EDGES * 32;
        spmm1_kernel<<<(unsigned)((threads + 255) / 256), 256>>>(adj_row, adj_col, vals);
    }
    // h4 = relu(h2 + b1) @ W2
    gemm2_kernel<<<(N_NODES + 63) / 64, 256>>>(b1, w2);
    // out = b2 (broadcast)
    {
        int n = N_NODES * OUTF / 4;
        init_out_kernel<<<(n + 255) / 256, 256>>>(out, b2);
    }
    // out += A @ h4
    {
        long long threads = (long long)N_EDGES * 16;
        spmm2_kernel<<<(unsigned)((threads + 255) / 256), 256>>>(adj_row, adj_col, vals, out);
    }
}

// round 2
// speedup vs baseline: 1.2112x; 1.2112x over previous
#include <cuda_runtime.h>
#include <cstdint>

#define N_NODES 100000
#define N_EDGES 1600000
#define IN_F    256
#define HID     128
#define OUTF    64

// Scratch (device globals: allocation-free per harness rules)
__device__ float g_h1[(size_t)N_NODES * HID];   // X@W1
__device__ float g_h2[(size_t)N_NODES * HID];   // spmm(h1)
__device__ float g_h4[(size_t)N_NODES * OUTF];  // relu(h2+b1)@W2

// Vectorized fp32 reduction to global (sm_90+): 4 floats per atomic op.
__device__ __forceinline__ void red_add_v4(float* p, float x, float y, float z, float w) {
    asm volatile("red.global.add.v4.f32 [%0], {%1, %2, %3, %4};"
                 :: "l"(p), "f"(x), "f"(y), "f"(z), "f"(w) : "memory");
}

__device__ __forceinline__ uint32_t f2tf32(float f) {
    uint32_t u;
    asm("cvt.rna.tf32.f32 %0, %1;" : "=r"(u) : "f"(f));
    return u;
}

__device__ __forceinline__ void mma_tf32(float c[4], const uint32_t a[4], const uint32_t b[2]) {
    asm volatile(
        "mma.sync.aligned.m16n8k8.row.col.f32.tf32.tf32.f32 "
        "{%0,%1,%2,%3}, {%4,%5,%6,%7}, {%8,%9}, {%0,%1,%2,%3};"
        : "+f"(c[0]), "+f"(c[1]), "+f"(c[2]), "+f"(c[3])
        : "r"(a[0]), "r"(a[1]), "r"(a[2]), "r"(a[3]), "r"(b[0]), "r"(b[1]));
}

// ---------------------------------------------------------------------------
// zero h2
// ---------------------------------------------------------------------------
__global__ void zero_h2_kernel() {
    size_t i = (size_t)blockIdx.x * blockDim.x + threadIdx.x;
    size_t n = (size_t)N_NODES * HID / 4;
    if (i < n) ((float4*)g_h2)[i] = make_float4(0.f, 0.f, 0.f, 0.f);
}

// ---------------------------------------------------------------------------
// GEMM1 (TF32 tensor): g_h1[M,128] = X[M,256] @ W1[256,128]
// Block tile 128x128, BK=32, 256 threads = 8 warps in 4(M)x2(N).
// Warp tile 32x64 -> 2(M)x8(N) m16n8k8 mmas per k-step.
// ---------------------------------------------------------------------------
#define G1_STRIDE 132
__global__ __launch_bounds__(256) void gemm1_tf32_kernel(const float* __restrict__ X,
                                                         const float* __restrict__ W1) {
    __shared__ uint32_t As[32 * G1_STRIDE];  // [k][m]
    __shared__ uint32_t Bs[32 * G1_STRIDE];  // [k][n]

    const int tid  = threadIdx.x;
    const int warp = tid >> 5;
    const int lane = tid & 31;
    const int wm   = warp >> 1;   // 0..3
    const int wn   = warp & 1;    // 0..1
    const int brow = blockIdx.x * 128;

    const int grp = lane >> 2;    // 0..7
    const int tig = lane & 3;     // 0..3

    float c[2][8][4];
#pragma unroll
    for (int mt = 0; mt < 2; mt++)
#pragma unroll
        for (int nt = 0; nt < 8; nt++)
#pragma unroll
            for (int i = 0; i < 4; i++) c[mt][nt][i] = 0.f;

    for (int k0 = 0; k0 < IN_F; k0 += 32) {
        // Load A tile 128x32 (transposed to [k][m])
#pragma unroll
        for (int i = 0; i < 4; i++) {
            int f  = tid + i * 256;      // 0..1023
            int r  = f >> 3;             // 0..127
            int kk = (f & 7) << 2;       // 0..28
            int gr = brow + r;
            float4 v = make_float4(0.f, 0.f, 0.f, 0.f);
            if (gr < N_NODES) v = *(const float4*)(X + (size_t)gr * IN_F + k0 + kk);
            As[(kk + 0) * G1_STRIDE + r] = f2tf32(v.x);
            As[(kk + 1) * G1_STRIDE + r] = f2tf32(v.y);
            As[(kk + 2) * G1_STRIDE + r] = f2tf32(v.z);
            As[(kk + 3) * G1_STRIDE + r] = f2tf32(v.w);
        }
        // Load B tile 32x128 ([k][n], same layout as W1)
#pragma unroll
        for (int i = 0; i < 4; i++) {
            int f  = tid + i * 256;
            int kr = f >> 5;             // 0..31
            int nc = (f & 31) << 2;      // 0..124
            float4 v = *(const float4*)(W1 + (size_t)(k0 + kr) * HID + nc);
            Bs[kr * G1_STRIDE + nc + 0] = f2tf32(v.x);
            Bs[kr * G1_STRIDE + nc + 1] = f2tf32(v.y);
            Bs[kr * G1_STRIDE + nc + 2] = f2tf32(v.z);
            Bs[kr * G1_STRIDE + nc + 3] = f2tf32(v.w);
        }
        __syncthreads();

#pragma unroll
        for (int ks = 0; ks < 32; ks += 8) {
            uint32_t a[2][4], b[8][2];
#pragma unroll
            for (int mt = 0; mt < 2; mt++) {
                int m0 = wm * 32 + mt * 16;
                a[mt][0] = As[(ks + tig) * G1_STRIDE + m0 + grp];
                a[mt][1] = As[(ks + tig) * G1_STRIDE + m0 + grp + 8];
                a[mt][2] = As[(ks + tig + 4) * G1_STRIDE + m0 + grp];
                a[mt][3] = As[(ks + tig + 4) * G1_STRIDE + m0 + grp + 8];
            }
#pragma unroll
            for (int nt = 0; nt < 8; nt++) {
                int n0 = wn * 64 + nt * 8;
                b[nt][0] = Bs[(ks + tig) * G1_STRIDE + n0 + grp];
                b[nt][1] = Bs[(ks + tig + 4) * G1_STRIDE + n0 + grp];
            }
#pragma unroll
            for (int mt = 0; mt < 2; mt++)
#pragma unroll
                for (int nt = 0; nt < 8; nt++)
                    mma_tf32(c[mt][nt], a[mt], b[nt]);
        }
        __syncthreads();
    }

    // Epilogue: c0,c1 -> row grp, cols 2*tig,2*tig+1 ; c2,c3 -> row grp+8
#pragma unroll
    for (int mt = 0; mt < 2; mt++) {
        int r0 = brow + wm * 32 + mt * 16 + grp;
        int r1 = r0 + 8;
#pragma unroll
        for (int nt = 0; nt < 8; nt++) {
            int col = wn * 64 + nt * 8 + 2 * tig;
            if (r0 < N_NODES)
                *(float2*)(g_h1 + (size_t)r0 * HID + col) =
                    make_float2(c[mt][nt][0], c[mt][nt][1]);
            if (r1 < N_NODES)
                *(float2*)(g_h1 + (size_t)r1 * HID + col) =
                    make_float2(c[mt][nt][2], c[mt][nt][3]);
        }
    }
}

// ---------------------------------------------------------------------------
// SpMM1: g_h2[row] += vals * g_h1[col]  (warp per edge, float4 per lane)
// ---------------------------------------------------------------------------
__global__ void spmm1_kernel(const int* __restrict__ row,
                             const int* __restrict__ col,
                             const float* __restrict__ vals) {
    long long t = (long long)blockIdx.x * blockDim.x + threadIdx.x;
    int e    = (int)(t >> 5);
    int lane = (int)(t & 31);
    if (e >= N_EDGES) return;
    int   r = __ldg(row + e);
    int   c = __ldg(col + e);
    float v = __ldg(vals + e);
    const float4 s = *(const float4*)(g_h1 + (size_t)c * HID + lane * 4);
    red_add_v4(g_h2 + (size_t)r * HID + lane * 4, s.x * v, s.y * v, s.z * v, s.w * v);
}

// ---------------------------------------------------------------------------
// GEMM2 (fused, fp32): g_h4[M,64] = relu(g_h2 + b1) @ W2[128,64]
// ---------------------------------------------------------------------------
__global__ __launch_bounds__(256) void gemm2_kernel(const float* __restrict__ B1,
                                                    const float* __restrict__ W2) {
    __shared__ float As[16 * 64];   // [k][m]
    __shared__ float Bs[16 * 64];   // [k][n]
    __shared__ float b1s[HID];

    const int tid = threadIdx.x;
    if (tid < HID) b1s[tid] = B1[tid];

    const int brow = blockIdx.x * 64;
    const int tx   = tid & 15;   // col group (x4)
    const int ty   = tid >> 4;   // row group (x4)

    float acc[4][4];
#pragma unroll
    for (int i = 0; i < 4; i++)
#pragma unroll
        for (int j = 0; j < 4; j++) acc[i][j] = 0.f;

    const int  arow   = tid >> 2;
    const int  ak     = (tid & 3) << 2;
    const int  grow   = brow + arow;
    const bool avalid = grow < N_NODES;

    __syncthreads();   // b1s visible

    for (int k0 = 0; k0 < HID; k0 += 16) {
        float4 av = make_float4(0.f, 0.f, 0.f, 0.f);
        if (avalid) {
            av = *(const float4*)(g_h2 + (size_t)grow * HID + k0 + ak);
            av.x = fmaxf(av.x + b1s[k0 + ak + 0], 0.f);
            av.y = fmaxf(av.y + b1s[k0 + ak + 1], 0.f);
            av.z = fmaxf(av.z + b1s[k0 + ak + 2], 0.f);
            av.w = fmaxf(av.w + b1s[k0 + ak + 3], 0.f);
        }
        As[(ak + 0) * 64 + arow] = av.x;
        As[(ak + 1) * 64 + arow] = av.y;
        As[(ak + 2) * 64 + arow] = av.z;
        As[(ak + 3) * 64 + arow] = av.w;

        {
            int br = tid >> 4;            // 0..15
            int bc = (tid & 15) << 2;     // 0..60
            *(float4*)(Bs + br * 64 + bc) =
                *(const float4*)(W2 + (size_t)(k0 + br) * OUTF + bc);
        }
        __syncthreads();

#pragma unroll
        for (int k = 0; k < 16; k++) {
            float4 a = *(float4*)(As + k * 64 + ty * 4);
            float4 b = *(float4*)(Bs + k * 64 + tx * 4);
            float aa[4] = {a.x, a.y, a.z, a.w};
            float bb[4] = {b.x, b.y, b.z, b.w};
#pragma unroll
            for (int i = 0; i < 4; i++)
#pragma unroll
                for (int j = 0; j < 4; j++) acc[i][j] += aa[i] * bb[j];
        }
        __syncthreads();
    }

#pragma unroll
    for (int i = 0; i < 4; i++) {
        int r = brow + ty * 4 + i;
        if (r < N_NODES)
            *(float4*)(g_h4 + (size_t)r * OUTF + tx * 4) =
                make_float4(acc[i][0], acc[i][1], acc[i][2], acc[i][3]);
    }
}

// ---------------------------------------------------------------------------
// init out = broadcast b2
// ---------------------------------------------------------------------------
__global__ void init_out_kernel(float* __restrict__ out, const float* __restrict__ B2) {
    int i = blockIdx.x * blockDim.x + threadIdx.x;   // over N*64/4 float4s
    if (i < N_NODES * OUTF / 4) {
        int j = i & 15;                               // float4 index within row
        float4 b = *(const float4*)(B2 + j * 4);
        ((float4*)out)[i] = b;
    }
}

// ---------------------------------------------------------------------------
// SpMM2: out[row] += vals * g_h4[col]  (16 threads per edge, float4 each)
// ---------------------------------------------------------------------------
__global__ void spmm2_kernel(const int* __restrict__ row,
                             const int* __restrict__ col,
                             const float* __restrict__ vals,
                             float* __restrict__ out) {
    long long t = (long long)blockIdx.x * blockDim.x + threadIdx.x;
    int e = (int)(t >> 4);
    int j = (int)(t & 15);
    if (e >= N_EDGES) return;
    int   r = __ldg(row + e);
    int   c = __ldg(col + e);
    float v = __ldg(vals + e);
    const float4 s = *(const float4*)(g_h4 + (size_t)c * OUTF + j * 4);
    red_add_v4(out + (size_t)r * OUTF + j * 4, s.x * v, s.y * v, s.z * v, s.w * v);
}

// ---------------------------------------------------------------------------
extern "C" void kernel_launch(void* const* d_in, const int* in_sizes, int n_in,
                              void* d_out, int out_size) {
    const float* x       = (const float*)d_in[0];
    const float* w1      = (const float*)d_in[1];
    const float* b1      = (const float*)d_in[2];
    const float* w2      = (const float*)d_in[3];
    const float* b2      = (const float*)d_in[4];
    const int*   adj_row = (const int*)d_in[5];
    const int*   adj_col = (const int*)d_in[6];
    const float* vals    = (const float*)d_in[7];
    float*       out     = (float*)d_out;

    (void)in_sizes; (void)n_in; (void)out_size;

    // zero h2 accumulator
    {
        int n = N_NODES * HID / 4;
        zero_h2_kernel<<<(n + 255) / 256, 256>>>();
    }
    // h1 = X @ W1 (TF32 tensor cores)
    gemm1_tf32_kernel<<<(N_NODES + 127) / 128, 256>>>(x, w1);
    // h2 = A @ h1  (edge scatter, v4 reductions)
    {
        long long threads = (long long)N_EDGES * 32;
        spmm1_kernel<<<(unsigned)((threads + 255) / 256), 256>>>(adj_row, adj_col, vals);
    }
    // h4 = relu(h2 + b1) @ W2
    gemm2_kernel<<<(N_NODES + 63) / 64, 256>>>(b1, w2);
    // out = b2 (broadcast)
    {
        int n = N_NODES * OUTF / 4;
        init_out_kernel<<<(n + 255) / 256, 256>>>(out, b2);
    }
    // out += A @ h4
    {
        long long threads = (long long)N_EDGES * 16;
        spmm2_kernel<<<(unsigned)((threads + 255) / 256), 256>>>(adj_row, adj_col, vals, out);
    }
}